// round 14
// baseline (speedup 1.0000x reference)
#include <cuda_runtime.h>
#include <cuda_bf16.h>
#include <cuda_fp16.h>
#include <math.h>
#include <stdint.h>

// Problem constants
#define BATCH   4
#define SEQ     2048
#define DMODEL  1024
#define NHEADS  16
#define DK      64
#define LORA_R  8
#define MTOT    (BATCH * SEQ)       // 8192
#define SCALING 2.0f
#define QSCALE  (0.125f * 1.4426950408889634f)   // fold log2(e)/sqrt(dk) into Q

// ---------------- scratch (device globals; no allocations allowed) ----------
__device__ float g_t[3 * MTOT * LORA_R];
__device__ __half g_xf[MTOT * DMODEL];            // x, fp16 (written by prep)
__device__ __half g_wf[4 * DMODEL * DMODEL];      // W^T fp16: [w][n][k]
__device__ __half g_af[MTOT * DMODEL];            // attention out, fp16
__device__ __half g_qh[MTOT * DMODEL];            // fp16 Q (pre-scaled log2e/8)
__device__ __half g_kh[MTOT * DMODEL];
__device__ __half g_vh[MTOT * DMODEL];

#define SMEM_SW(off) ((off) ^ (((off) >> 3) & 0x70))

__device__ __forceinline__ uint32_t smem_u32(const void* p) {
    uint32_t a;
    asm("{ .reg .u64 t; cvta.to.shared.u64 t, %1; cvt.u32.u64 %0, t; }" : "=r"(a) : "l"(p));
    return a;
}

// ---------------- mma / ldmatrix / cp.async helpers --------------------------
__device__ __forceinline__ void mma16h(float* d, unsigned a0, unsigned a1, unsigned a2,
                                       unsigned a3, unsigned b0, unsigned b1) {
    asm volatile(
        "mma.sync.aligned.m16n8k16.row.col.f32.f16.f16.f32 "
        "{%0,%1,%2,%3}, {%4,%5,%6,%7}, {%8,%9}, {%0,%1,%2,%3};\n"
        : "+f"(d[0]), "+f"(d[1]), "+f"(d[2]), "+f"(d[3])
        : "r"(a0), "r"(a1), "r"(a2), "r"(a3), "r"(b0), "r"(b1));
}
__device__ __forceinline__ void ldsm_x4(unsigned& r0, unsigned& r1, unsigned& r2,
                                        unsigned& r3, uint32_t addr) {
    asm volatile("ldmatrix.sync.aligned.m8n8.x4.shared.b16 {%0,%1,%2,%3}, [%4];"
                 : "=r"(r0), "=r"(r1), "=r"(r2), "=r"(r3) : "r"(addr));
}
__device__ __forceinline__ void ldsm_x4_t(unsigned& r0, unsigned& r1, unsigned& r2,
                                          unsigned& r3, uint32_t addr) {
    asm volatile("ldmatrix.sync.aligned.m8n8.x4.trans.shared.b16 {%0,%1,%2,%3}, [%4];"
                 : "=r"(r0), "=r"(r1), "=r"(r2), "=r"(r3) : "r"(addr));
}
__device__ __forceinline__ void cp16(uint32_t dst, const void* src) {
    asm volatile("cp.async.cg.shared.global [%0], [%1], 16;" :: "r"(dst), "l"(src));
}
#define CP_COMMIT()  asm volatile("cp.async.commit_group;" ::: "memory")
#define CP_WAIT(n)   asm volatile("cp.async.wait_group %0;" :: "n"(n) : "memory")
__device__ __forceinline__ float ex2(float x) {
    float r;
    asm("ex2.approx.f32 %0, %1;" : "=f"(r) : "f"(x));
    return r;
}

// ---------------- kernel 0+1 merged: weight transpose/fp16 + LoRA down ------
__global__ void prep_kernel(const float* __restrict__ x,
                            const float* __restrict__ w0, const float* __restrict__ w1,
                            const float* __restrict__ w2, const float* __restrict__ w3,
                            const float* __restrict__ aq, const float* __restrict__ ak,
                            const float* __restrict__ av) {
    __shared__ float tile[32][33];
    __shared__ float as[3][32][LORA_R];
    const int tid = threadIdx.x;

    if (blockIdx.x < 4096) {
        const int wsel = blockIdx.x >> 10;
        const int rem  = blockIdx.x & 1023;
        const int k0 = (rem >> 5) * 32, n0 = (rem & 31) * 32;
        const float* W = (wsel == 0) ? w0 : (wsel == 1) ? w1 : (wsel == 2) ? w2 : w3;
        const size_t off = (size_t)wsel * DMODEL * DMODEL;
        const int tx = tid & 31, ty = tid >> 5;
        #pragma unroll
        for (int i = 0; i < 4; i++) {
            int r = ty + i * 8;
            tile[r][tx] = W[(size_t)(k0 + r) * DMODEL + n0 + tx];
        }
        __syncthreads();
        #pragma unroll
        for (int i = 0; i < 4; i++) {
            int r = ty + i * 8;
            g_wf[off + (size_t)(n0 + r) * DMODEL + k0 + tx] = __float2half_rn(tile[tx][r]);
        }
    } else {
        const int m0  = (blockIdx.x - 4096) * 32;
        const int row = tid >> 3;
        const int r   = tid & 7;
        float acc0 = 0.f, acc1 = 0.f, acc2 = 0.f;
        for (int k0 = 0; k0 < DMODEL; k0 += 32) {
            #pragma unroll
            for (int idx = tid; idx < 32 * 32; idx += 256) {
                int rr = idx >> 5, kk = idx & 31;
                float v = x[(size_t)(m0 + rr) * DMODEL + k0 + kk];
                tile[rr][kk] = v;
                g_xf[(size_t)(m0 + rr) * DMODEL + k0 + kk] = __float2half_rn(v);
            }
            for (int idx = tid; idx < 3 * 32 * LORA_R; idx += 256) {
                int w = idx >> 8, rem2 = idx & 255;
                int kk = rem2 >> 3, rj = rem2 & 7;
                const float* a = (w == 0) ? aq : ((w == 1) ? ak : av);
                as[w][kk][rj] = a[(size_t)(k0 + kk) * LORA_R + rj];
            }
            __syncthreads();
            #pragma unroll
            for (int kk = 0; kk < 32; kk++) {
                float xv = tile[row][kk];
                acc0 += xv * as[0][kk][r];
                acc1 += xv * as[1][kk][r];
                acc2 += xv * as[2][kk][r];
            }
            __syncthreads();
        }
        const int m = m0 + row;
        g_t[0 * MTOT * LORA_R + m * LORA_R + r] = acc0;
        g_t[1 * MTOT * LORA_R + m * LORA_R + r] = acc1;
        g_t[2 * MTOT * LORA_R + m * LORA_R + r] = acc2;
    }
}

// ---------------- gemm core: fp16, 2-stage cp.async, occ 3 ------------------
// CTA 128x128, BK=64, 256 threads, 1 barrier/tile, register-lean addressing.
#define GA_PL 16384
#define GBUF  32768                          // A plane + B plane per stage
#define GSMEM (2 * GBUF + LORA_R * 128 * 4)  // 69632

extern __shared__ char gsm[];

__device__ __forceinline__ void gemm_core(
        const __half* __restrict__ A, const __half* __restrict__ Wt,
        const float* __restrict__ bias,
        const float* __restrict__ t, const float* __restrict__ u,
        float* __restrict__ out32, __half* __restrict__ out16,
        float oscale, int m0, int n0) {
    float* Us = (float*)(gsm + 2 * GBUF);

    const int tid  = threadIdx.x;
    const int warp = tid >> 5;
    const int lane = tid & 31;
    const int g  = lane >> 2;
    const int tq = lane & 3;
    const int wm = warp >> 2;
    const int wn = warp & 3;

    if (u != nullptr) {
        #pragma unroll
        for (int p = 0; p < 4; p++) {
            int idx = tid + p * 256;
            Us[idx] = u[(size_t)(idx >> 7) * DMODEL + n0 + (idx & 127)];
        }
    }

    const uint32_t sbase = smem_u32(gsm);

    // staging: row = tid>>1, 4 16B-chunks at c8 = (tid&1)*4 + i
    const int srow = tid >> 1;
    const int shq  = (tid & 1) * 4;
    const __half* Ap = A  + (size_t)(m0 + srow) * DMODEL + shq * 8;
    const __half* Bp = Wt + (size_t)(n0 + srow) * DMODEL + shq * 8;
    const uint32_t s_off = srow * 128 + shq * 16;

    #define STAGE(BUF, TILE) do {                                              \
        const int ko_ = (TILE) * 64;                                           \
        const uint32_t sd_ = sbase + (BUF) * GBUF;                             \
        _Pragma("unroll")                                                      \
        for (int i = 0; i < 4; i++) {                                          \
            cp16(sd_ + SMEM_SW(s_off + i * 16),         Ap + ko_ + i * 8);     \
            cp16(sd_ + GA_PL + SMEM_SW(s_off + i * 16), Bp + ko_ + i * 8);     \
        }                                                                      \
    } while (0)

    STAGE(0, 0);
    CP_COMMIT();

    // fragment base byte-offsets (pre-swizzle; compile-time steps added at use)
    const uint32_t a_base = (wm * 64 + (lane & 15)) * 128 + (lane >> 4) * 16;
    const uint32_t b_base = (wn * 32 + ((lane >> 4) << 3) + (lane & 7)) * 128 +
                            ((lane >> 3) & 1) * 16;

    float D[4][4][4] = {};
    const int NT = DMODEL / 64;   // 16

    for (int tile = 0; tile < NT; tile++) {
        CP_WAIT(0);
        __syncthreads();   // tile data visible; all warps past compute(tile-1)

        if (tile + 1 < NT) {
            STAGE((tile + 1) & 1, tile + 1);
            CP_COMMIT();
        }

        const uint32_t ab = sbase + (tile & 1) * GBUF;
        const uint32_t bb = ab + GA_PL;

        #pragma unroll
        for (int ks = 0; ks < 4; ks++) {
            unsigned bf[4][2];
            #pragma unroll
            for (int ntp = 0; ntp < 2; ntp++) {
                unsigned b0, b1, b2, b3;
                ldsm_x4(b0, b1, b2, b3,
                        bb + SMEM_SW(b_base + ntp * 2048 + ks * 32));
                bf[ntp * 2][0] = b0; bf[ntp * 2][1] = b1;
                bf[ntp * 2 + 1][0] = b2; bf[ntp * 2 + 1][1] = b3;
            }
            #pragma unroll
            for (int mt = 0; mt < 4; mt++) {
                unsigned a0, a1, a2, a3;
                ldsm_x4(a0, a1, a2, a3,
                        ab + SMEM_SW(a_base + mt * 2048 + ks * 32));
                #pragma unroll
                for (int nt = 0; nt < 4; nt++)
                    mma16h(D[mt][nt], a0, a1, a2, a3, bf[nt][0], bf[nt][1]);
            }
        }
    }
    #undef STAGE

    // ---- epilogue ----
    #pragma unroll
    for (int mt = 0; mt < 4; mt++) {
        #pragma unroll
        for (int half_ = 0; half_ < 2; half_++) {
            const int m = m0 + wm * 64 + mt * 16 + g + half_ * 8;
            float trow[LORA_R];
            if (t != nullptr) {
                float4 t0 = *(const float4*)&t[(size_t)m * LORA_R];
                float4 t1 = *(const float4*)&t[(size_t)m * LORA_R + 4];
                trow[0] = t0.x; trow[1] = t0.y; trow[2] = t0.z; trow[3] = t0.w;
                trow[4] = t1.x; trow[5] = t1.y; trow[6] = t1.z; trow[7] = t1.w;
            }
            #pragma unroll
            for (int nt = 0; nt < 4; nt++) {
                const int ncl = wn * 32 + nt * 8 + 2 * tq;
                float v0 = D[mt][nt][half_ * 2 + 0] + bias[n0 + ncl];
                float v1 = D[mt][nt][half_ * 2 + 1] + bias[n0 + ncl + 1];
                if (t != nullptr) {
                    float l0 = 0.f, l1 = 0.f;
                    #pragma unroll
                    for (int r = 0; r < LORA_R; r++) {
                        l0 += trow[r] * Us[r * 128 + ncl];
                        l1 += trow[r] * Us[r * 128 + ncl + 1];
                    }
                    v0 += SCALING * l0;
                    v1 += SCALING * l1;
                }
                if (out16 != nullptr) {
                    __half2 hv = __floats2half2_rn(v0 * oscale, v1 * oscale);
                    *(__half2*)&out16[(size_t)m * DMODEL + n0 + ncl] = hv;
                } else {
                    *(float2*)&out32[(size_t)m * DMODEL + n0 + ncl] = make_float2(v0, v1);
                }
            }
        }
    }
}

// merged QKV launch
__global__ __launch_bounds__(256, 3)
void gemm_qkv_kernel(const __half* __restrict__ xf, const __half* __restrict__ wf,
                     const float* __restrict__ b_q, const float* __restrict__ b_k,
                     const float* __restrict__ b_v, const float* __restrict__ tb,
                     const float* __restrict__ u_q, const float* __restrict__ u_k,
                     const float* __restrict__ u_v,
                     __half* __restrict__ qh, __half* __restrict__ kh,
                     __half* __restrict__ vh) {
    const int z = blockIdx.z;
    const __half* Wt = wf + (size_t)z * DMODEL * DMODEL;
    const float* bias = (z == 0) ? b_q : (z == 1) ? b_k : b_v;
    const float* u    = (z == 0) ? u_q : (z == 1) ? u_k : u_v;
    const float* t    = tb + (size_t)z * MTOT * LORA_R;
    __half* out       = (z == 0) ? qh : (z == 1) ? kh : vh;
    const float osc   = (z == 0) ? QSCALE : 1.0f;
    gemm_core(xf, Wt, bias, t, u, nullptr, out, osc,
              blockIdx.y * 128, blockIdx.x * 128);
}

__global__ __launch_bounds__(256, 3)
void gemm_o_kernel(const __half* __restrict__ af, const __half* __restrict__ wf,
                   const float* __restrict__ b_o, float* __restrict__ out) {
    gemm_core(af, wf + 3ULL * DMODEL * DMODEL, b_o, nullptr, nullptr,
              out, nullptr, 1.0f, blockIdx.y * 128, blockIdx.x * 128);
}

// ---------------- kernel 3: flash attention ---------------------------------
// Br=64 (4 warps, 128 threads, occ 4), Bc=32, P in regs, Q frags hoisted,
// 3-stage cp.async K/V, row-sums via ones-mma.
#define ATS 4096
#define H1X2 0x3C003C00u   // half2(1.0, 1.0)

__global__ __launch_bounds__(128, 4) void attn_kernel() {
    __shared__ __align__(16) __half Qs[64 * 64];        // 8 KB
    __shared__ __align__(16) __half KVs[3][2][32 * 64]; // 24 KB

    const int tid  = threadIdx.x;
    const int warp = tid >> 5;
    const int lane = tid & 31;
    const int g = lane >> 2;
    const int t = lane & 3;
    const int r0 = warp * 16;
    const int q0 = blockIdx.x * 64;
    const int bh = blockIdx.y;
    const int b = bh >> 4, h = bh & 15;

    const __half* qbase = g_qh + (size_t)b * SEQ * DMODEL + h * DK;
    const __half* kbase = g_kh + (size_t)b * SEQ * DMODEL + h * DK;
    const __half* vbase = g_vh + (size_t)b * SEQ * DMODEL + h * DK;

    #pragma unroll
    for (int i = 0; i < 4; i++) {
        int idx = tid + i * 128;
        int row = idx >> 3, c8 = idx & 7;
        uint32_t sw = SMEM_SW(row * 128 + c8 * 16);
        *(uint4*)((char*)Qs + sw) = *(const uint4*)(qbase + (size_t)(q0 + row) * DMODEL + c8 * 8);
    }

    const uint32_t qb = smem_u32(Qs);
    const uint32_t kvb = smem_u32(KVs);

    const int row0s = tid >> 3;
    const int row1s = row0s + 16;
    const int c8s   = tid & 7;
    const uint32_t ssw0 = SMEM_SW(row0s * 128 + c8s * 16);
    const uint32_t ssw1 = SMEM_SW(row1s * 128 + c8s * 16);
    const __half* kp0 = kbase + (size_t)row0s * DMODEL + c8s * 8;
    const __half* kp1 = kbase + (size_t)row1s * DMODEL + c8s * 8;
    const __half* vp0 = vbase + (size_t)row0s * DMODEL + c8s * 8;
    const __half* vp1 = vbase + (size_t)row1s * DMODEL + c8s * 8;

    #define ATT_STAGE(SLOT, TILE) do {                                         \
        const size_t go_ = (size_t)(TILE) * 32 * DMODEL;                       \
        const uint32_t kd_ = kvb + (SLOT) * 2 * ATS;                           \
        cp16(kd_ + ssw0,       kp0 + go_);                                     \
        cp16(kd_ + ssw1,       kp1 + go_);                                     \
        cp16(kd_ + ATS + ssw0, vp0 + go_);                                     \
        cp16(kd_ + ATS + ssw1, vp1 + go_);                                     \
    } while (0)

    ATT_STAGE(0, 0);
    CP_COMMIT();
    ATT_STAGE(1, 1);
    CP_COMMIT();

    uint32_t kfo[4][2];
    #pragma unroll
    for (int ks = 0; ks < 4; ks++)
        #pragma unroll
        for (int ntp = 0; ntp < 2; ntp++)
            kfo[ks][ntp] = SMEM_SW((ntp * 16 + ((lane >> 4) << 3) + (lane & 7)) * 128 +
                                   ((lane >> 3) & 1) * 16 + ks * 32);
    uint32_t vfo[2][4];
    #pragma unroll
    for (int kp_ = 0; kp_ < 2; kp_++)
        #pragma unroll
        for (int ntp = 0; ntp < 4; ntp++)
            vfo[kp_][ntp] = SMEM_SW((kp_ * 16 + ((lane >> 3) & 1) * 8 + (lane & 7)) * 128 +
                                    ntp * 32 + (lane >> 4) * 16);

    __syncthreads();
    unsigned qf[4][4];
    #pragma unroll
    for (int ks = 0; ks < 4; ks++)
        ldsm_x4(qf[ks][0], qf[ks][1], qf[ks][2], qf[ks][3],
                qb + SMEM_SW((r0 + (lane & 15)) * 128 + ks * 32 + (lane >> 4) * 16));

    float O[8][4] = {};
    float rsum[4] = {};

    const int NKV = SEQ / 32;
    for (int tile = 0; tile < NKV; tile++) {
        if (tile + 1 < NKV) { CP_WAIT(1); } else { CP_WAIT(0); }
        __syncthreads();

        if (tile + 2 < NKV) {
            ATT_STAGE((tile + 2) % 3, tile + 2);
            CP_COMMIT();
        }

        const uint32_t kb_t = kvb + (tile % 3) * 2 * ATS;
        const uint32_t vb_t = kb_t + ATS;

        float S[4][4] = {};
        #pragma unroll
        for (int ks = 0; ks < 4; ks++) {
            #pragma unroll
            for (int ntp = 0; ntp < 2; ntp++) {
                unsigned b0, b1, b2, b3;
                ldsm_x4(b0, b1, b2, b3, kb_t + kfo[ks][ntp]);
                mma16h(S[ntp * 2],     qf[ks][0], qf[ks][1], qf[ks][2], qf[ks][3], b0, b1);
                mma16h(S[ntp * 2 + 1], qf[ks][0], qf[ks][1], qf[ks][2], qf[ks][3], b2, b3);
            }
        }

        unsigned ph[8];
        #pragma unroll
        for (int nt = 0; nt < 4; nt++) {
            float p0 = ex2(S[nt][0]), p1 = ex2(S[nt][1]);
            float p2 = ex2(S[nt][2]), p3 = ex2(S[nt][3]);
            __half2 h01 = __floats2half2_rn(p0, p1);
            __half2 h23 = __floats2half2_rn(p2, p3);
            ph[nt * 2]     = *(unsigned*)&h01;
            ph[nt * 2 + 1] = *(unsigned*)&h23;
        }
        mma16h(rsum, ph[0], ph[1], ph[2], ph[3], H1X2, H1X2);
        mma16h(rsum, ph[4], ph[5], ph[6], ph[7], H1X2, H1X2);

        #pragma unroll
        for (int kp_ = 0; kp_ < 2; kp_++) {
            unsigned a0 = ph[kp_ * 4 + 0], a1 = ph[kp_ * 4 + 1];
            unsigned a2 = ph[kp_ * 4 + 2], a3 = ph[kp_ * 4 + 3];
            #pragma unroll
            for (int ntp = 0; ntp < 4; ntp++) {
                unsigned b0, b1, b2, b3;
                ldsm_x4_t(b0, b1, b2, b3, vb_t + vfo[kp_][ntp]);
                mma16h(O[ntp * 2],     a0, a1, a2, a3, b0, b1);
                mma16h(O[ntp * 2 + 1], a0, a1, a2, a3, b2, b3);
            }
        }
    }
    #undef ATT_STAGE

    float inv0 = 1.0f / rsum[0], inv1 = 1.0f / rsum[2];
    const size_t row0 = ((size_t)b * SEQ + q0 + r0 + g) * DMODEL + h * DK;
    const size_t row1 = row0 + 8 * DMODEL;
    #pragma unroll
    for (int nt = 0; nt < 8; nt++) {
        const int c = nt * 8 + 2 * t;
        *(__half2*)&g_af[row0 + c] = __floats2half2_rn(O[nt][0] * inv0, O[nt][1] * inv0);
        *(__half2*)&g_af[row1 + c] = __floats2half2_rn(O[nt][2] * inv1, O[nt][3] * inv1);
    }
}

// ---------------- launch ----------------------------------------------------
extern "C" void kernel_launch(void* const* d_in, const int* in_sizes, int n_in,
                              void* d_out, int out_size) {
    const float* x   = (const float*)d_in[0];
    const float* w_q = (const float*)d_in[1];
    const float* b_q = (const float*)d_in[2];
    const float* w_k = (const float*)d_in[3];
    const float* b_k = (const float*)d_in[4];
    const float* w_v = (const float*)d_in[5];
    const float* b_v = (const float*)d_in[6];
    const float* w_o = (const float*)d_in[7];
    const float* b_o = (const float*)d_in[8];
    const float* a_q = (const float*)d_in[9];
    const float* u_q = (const float*)d_in[10];
    const float* a_k = (const float*)d_in[11];
    const float* u_k = (const float*)d_in[12];
    const float* a_v = (const float*)d_in[13];
    const float* u_v = (const float*)d_in[14];

    float* t_ptr;
    __half *xf, *wf, *af, *qh, *kh, *vh;
    cudaGetSymbolAddress((void**)&t_ptr, g_t);
    cudaGetSymbolAddress((void**)&xf, g_xf);
    cudaGetSymbolAddress((void**)&wf, g_wf);
    cudaGetSymbolAddress((void**)&af, g_af);
    cudaGetSymbolAddress((void**)&qh, g_qh);
    cudaGetSymbolAddress((void**)&kh, g_kh);
    cudaGetSymbolAddress((void**)&vh, g_vh);

    // 0+1) merged prep
    prep_kernel<<<4096 + MTOT / 32, 256>>>(x, w_q, w_k, w_v, w_o, a_q, a_k, a_v);

    // 2) merged QKV projections
    cudaFuncSetAttribute(gemm_qkv_kernel, cudaFuncAttributeMaxDynamicSharedMemorySize, GSMEM);
    cudaFuncSetAttribute(gemm_o_kernel, cudaFuncAttributeMaxDynamicSharedMemorySize, GSMEM);
    dim3 qkv_grid(DMODEL / 128, MTOT / 128, 3);
    gemm_qkv_kernel<<<qkv_grid, 256, GSMEM>>>(xf, wf, b_q, b_k, b_v, t_ptr,
                                              u_q, u_k, u_v, qh, kh, vh);

    // 3) attention (Br=64, occ 4)
    dim3 agrid(SEQ / 64, BATCH * NHEADS);
    attn_kernel<<<agrid, 128>>>();

    // 4) output projection
    dim3 ogrid(DMODEL / 128, MTOT / 128);
    gemm_o_kernel<<<ogrid, 256, GSMEM>>>(af, wf, b_o, (float*)d_out);
}

// round 15
// speedup vs baseline: 1.4489x; 1.4489x over previous
#include <cuda_runtime.h>
#include <cuda_bf16.h>
#include <cuda_fp16.h>
#include <math.h>
#include <stdint.h>

// Problem constants
#define BATCH   4
#define SEQ     2048
#define DMODEL  1024
#define NHEADS  16
#define DK      64
#define LORA_R  8
#define MTOT    (BATCH * SEQ)       // 8192
#define SCALING 2.0f
#define QSCALE  (0.125f * 1.4426950408889634f)   // fold log2(e)/sqrt(dk) into Q

// ---------------- scratch (device globals; no allocations allowed) ----------
__device__ float g_t[3 * MTOT * LORA_R];
__device__ __half g_xf[MTOT * DMODEL];            // x, fp16 (written by prep)
__device__ __half g_wf[4 * DMODEL * DMODEL];      // W^T fp16: [w][n][k]
__device__ __half g_af[MTOT * DMODEL];            // attention out, fp16
__device__ __half g_qh[MTOT * DMODEL];            // fp16 Q (pre-scaled log2e/8)
__device__ __half g_kh[MTOT * DMODEL];
__device__ __half g_vh[MTOT * DMODEL];

#define SMEM_SW(off) ((off) ^ (((off) >> 3) & 0x70))

__device__ __forceinline__ uint32_t smem_u32(const void* p) {
    uint32_t a;
    asm("{ .reg .u64 t; cvta.to.shared.u64 t, %1; cvt.u32.u64 %0, t; }" : "=r"(a) : "l"(p));
    return a;
}

// ---------------- mma / ldmatrix / cp.async helpers --------------------------
__device__ __forceinline__ void mma16h(float* d, unsigned a0, unsigned a1, unsigned a2,
                                       unsigned a3, unsigned b0, unsigned b1) {
    asm volatile(
        "mma.sync.aligned.m16n8k16.row.col.f32.f16.f16.f32 "
        "{%0,%1,%2,%3}, {%4,%5,%6,%7}, {%8,%9}, {%0,%1,%2,%3};\n"
        : "+f"(d[0]), "+f"(d[1]), "+f"(d[2]), "+f"(d[3])
        : "r"(a0), "r"(a1), "r"(a2), "r"(a3), "r"(b0), "r"(b1));
}
__device__ __forceinline__ void ldsm_x4(unsigned& r0, unsigned& r1, unsigned& r2,
                                        unsigned& r3, uint32_t addr) {
    asm volatile("ldmatrix.sync.aligned.m8n8.x4.shared.b16 {%0,%1,%2,%3}, [%4];"
                 : "=r"(r0), "=r"(r1), "=r"(r2), "=r"(r3) : "r"(addr));
}
__device__ __forceinline__ void ldsm_x4_t(unsigned& r0, unsigned& r1, unsigned& r2,
                                          unsigned& r3, uint32_t addr) {
    asm volatile("ldmatrix.sync.aligned.m8n8.x4.trans.shared.b16 {%0,%1,%2,%3}, [%4];"
                 : "=r"(r0), "=r"(r1), "=r"(r2), "=r"(r3) : "r"(addr));
}
__device__ __forceinline__ void cp16(uint32_t dst, const void* src) {
    asm volatile("cp.async.cg.shared.global [%0], [%1], 16;" :: "r"(dst), "l"(src));
}
#define CP_COMMIT()  asm volatile("cp.async.commit_group;" ::: "memory")
#define CP_WAIT(n)   asm volatile("cp.async.wait_group %0;" :: "n"(n) : "memory")
__device__ __forceinline__ float ex2(float x) {
    float r;
    asm("ex2.approx.f32 %0, %1;" : "=f"(r) : "f"(x));
    return r;
}

// ---------------- kernel 0+1 merged: weight transpose/fp16 + LoRA down ------
__global__ void prep_kernel(const float* __restrict__ x,
                            const float* __restrict__ w0, const float* __restrict__ w1,
                            const float* __restrict__ w2, const float* __restrict__ w3,
                            const float* __restrict__ aq, const float* __restrict__ ak,
                            const float* __restrict__ av) {
    __shared__ float tile[32][33];
    __shared__ float as[3][32][LORA_R];
    const int tid = threadIdx.x;

    if (blockIdx.x < 4096) {
        const int wsel = blockIdx.x >> 10;
        const int rem  = blockIdx.x & 1023;
        const int k0 = (rem >> 5) * 32, n0 = (rem & 31) * 32;
        const float* W = (wsel == 0) ? w0 : (wsel == 1) ? w1 : (wsel == 2) ? w2 : w3;
        const size_t off = (size_t)wsel * DMODEL * DMODEL;
        const int tx = tid & 31, ty = tid >> 5;
        #pragma unroll
        for (int i = 0; i < 4; i++) {
            int r = ty + i * 8;
            tile[r][tx] = W[(size_t)(k0 + r) * DMODEL + n0 + tx];
        }
        __syncthreads();
        #pragma unroll
        for (int i = 0; i < 4; i++) {
            int r = ty + i * 8;
            g_wf[off + (size_t)(n0 + r) * DMODEL + k0 + tx] = __float2half_rn(tile[tx][r]);
        }
    } else {
        const int m0  = (blockIdx.x - 4096) * 32;
        const int row = tid >> 3;
        const int r   = tid & 7;
        float acc0 = 0.f, acc1 = 0.f, acc2 = 0.f;
        for (int k0 = 0; k0 < DMODEL; k0 += 32) {
            #pragma unroll
            for (int idx = tid; idx < 32 * 32; idx += 256) {
                int rr = idx >> 5, kk = idx & 31;
                float v = x[(size_t)(m0 + rr) * DMODEL + k0 + kk];
                tile[rr][kk] = v;
                g_xf[(size_t)(m0 + rr) * DMODEL + k0 + kk] = __float2half_rn(v);
            }
            for (int idx = tid; idx < 3 * 32 * LORA_R; idx += 256) {
                int w = idx >> 8, rem2 = idx & 255;
                int kk = rem2 >> 3, rj = rem2 & 7;
                const float* a = (w == 0) ? aq : ((w == 1) ? ak : av);
                as[w][kk][rj] = a[(size_t)(k0 + kk) * LORA_R + rj];
            }
            __syncthreads();
            #pragma unroll
            for (int kk = 0; kk < 32; kk++) {
                float xv = tile[row][kk];
                acc0 += xv * as[0][kk][r];
                acc1 += xv * as[1][kk][r];
                acc2 += xv * as[2][kk][r];
            }
            __syncthreads();
        }
        const int m = m0 + row;
        g_t[0 * MTOT * LORA_R + m * LORA_R + r] = acc0;
        g_t[1 * MTOT * LORA_R + m * LORA_R + r] = acc1;
        g_t[2 * MTOT * LORA_R + m * LORA_R + r] = acc2;
    }
}

// ---------------- gemm core: fp16, 3-stage cp.async (R13 pipeline) ----------
// CTA 128x128, BK=64, 256 threads, wait(1) depth-2 overlap, 1 barrier/tile.
// Register-lean inline addressing (R14's only keeper).
#define GA_PL 16384
#define GBUF  32768                          // A plane + B plane per stage
#define GSMEM (3 * GBUF + LORA_R * 128 * 4)  // 102400

extern __shared__ char gsm[];

__device__ __forceinline__ void gemm_core(
        const __half* __restrict__ A, const __half* __restrict__ Wt,
        const float* __restrict__ bias,
        const float* __restrict__ t, const float* __restrict__ u,
        float* __restrict__ out32, __half* __restrict__ out16,
        float oscale, int m0, int n0) {
    float* Us = (float*)(gsm + 3 * GBUF);

    const int tid  = threadIdx.x;
    const int warp = tid >> 5;
    const int lane = tid & 31;
    const int g  = lane >> 2;
    const int tq = lane & 3;
    const int wm = warp >> 2;
    const int wn = warp & 3;

    if (u != nullptr) {
        #pragma unroll
        for (int p = 0; p < 4; p++) {
            int idx = tid + p * 256;
            Us[idx] = u[(size_t)(idx >> 7) * DMODEL + n0 + (idx & 127)];
        }
    }

    const uint32_t sbase = smem_u32(gsm);

    // staging: row = tid>>1, 4 16B-chunks at c8 = (tid&1)*4 + i
    const int srow = tid >> 1;
    const int shq  = (tid & 1) * 4;
    const __half* Ap = A  + (size_t)(m0 + srow) * DMODEL + shq * 8;
    const __half* Bp = Wt + (size_t)(n0 + srow) * DMODEL + shq * 8;
    const uint32_t s_off = srow * 128 + shq * 16;

    #define STAGE(BUF, TILE) do {                                              \
        const int ko_ = (TILE) * 64;                                           \
        const uint32_t sd_ = sbase + (BUF) * GBUF;                             \
        _Pragma("unroll")                                                      \
        for (int i = 0; i < 4; i++) {                                          \
            cp16(sd_ + SMEM_SW(s_off + i * 16),         Ap + ko_ + i * 8);     \
            cp16(sd_ + GA_PL + SMEM_SW(s_off + i * 16), Bp + ko_ + i * 8);     \
        }                                                                      \
    } while (0)

    STAGE(0, 0);
    CP_COMMIT();
    STAGE(1, 1);
    CP_COMMIT();

    // fragment base byte-offsets (pre-swizzle; compile-time steps folded at use)
    const uint32_t a_base = (wm * 64 + (lane & 15)) * 128 + (lane >> 4) * 16;
    const uint32_t b_base = (wn * 32 + ((lane >> 4) << 3) + (lane & 7)) * 128 +
                            ((lane >> 3) & 1) * 16;

    float D[4][4][4] = {};
    const int NT = DMODEL / 64;   // 16

    for (int tile = 0; tile < NT; tile++) {
        if (tile + 1 < NT) { CP_WAIT(1); } else { CP_WAIT(0); }
        __syncthreads();   // stage `tile` visible; all warps done computing tile-1

        // stage tile+2 into slot (tile+2)%3 == slot of tile-1 (barrier-protected)
        if (tile + 2 < NT) {
            STAGE((tile + 2) % 3, tile + 2);
            CP_COMMIT();
        }

        const uint32_t ab = sbase + (tile % 3) * GBUF;
        const uint32_t bb = ab + GA_PL;

        #pragma unroll
        for (int ks = 0; ks < 4; ks++) {
            unsigned bf[4][2];
            #pragma unroll
            for (int ntp = 0; ntp < 2; ntp++) {
                unsigned b0, b1, b2, b3;
                ldsm_x4(b0, b1, b2, b3,
                        bb + SMEM_SW(b_base + ntp * 2048 + ks * 32));
                bf[ntp * 2][0] = b0; bf[ntp * 2][1] = b1;
                bf[ntp * 2 + 1][0] = b2; bf[ntp * 2 + 1][1] = b3;
            }
            #pragma unroll
            for (int mt = 0; mt < 4; mt++) {
                unsigned a0, a1, a2, a3;
                ldsm_x4(a0, a1, a2, a3,
                        ab + SMEM_SW(a_base + mt * 2048 + ks * 32));
                #pragma unroll
                for (int nt = 0; nt < 4; nt++)
                    mma16h(D[mt][nt], a0, a1, a2, a3, bf[nt][0], bf[nt][1]);
            }
        }
    }
    #undef STAGE

    // ---- epilogue ----
    #pragma unroll
    for (int mt = 0; mt < 4; mt++) {
        #pragma unroll
        for (int half_ = 0; half_ < 2; half_++) {
            const int m = m0 + wm * 64 + mt * 16 + g + half_ * 8;
            float trow[LORA_R];
            if (t != nullptr) {
                float4 t0 = *(const float4*)&t[(size_t)m * LORA_R];
                float4 t1 = *(const float4*)&t[(size_t)m * LORA_R + 4];
                trow[0] = t0.x; trow[1] = t0.y; trow[2] = t0.z; trow[3] = t0.w;
                trow[4] = t1.x; trow[5] = t1.y; trow[6] = t1.z; trow[7] = t1.w;
            }
            #pragma unroll
            for (int nt = 0; nt < 4; nt++) {
                const int ncl = wn * 32 + nt * 8 + 2 * tq;
                float v0 = D[mt][nt][half_ * 2 + 0] + bias[n0 + ncl];
                float v1 = D[mt][nt][half_ * 2 + 1] + bias[n0 + ncl + 1];
                if (t != nullptr) {
                    float l0 = 0.f, l1 = 0.f;
                    #pragma unroll
                    for (int r = 0; r < LORA_R; r++) {
                        l0 += trow[r] * Us[r * 128 + ncl];
                        l1 += trow[r] * Us[r * 128 + ncl + 1];
                    }
                    v0 += SCALING * l0;
                    v1 += SCALING * l1;
                }
                if (out16 != nullptr) {
                    __half2 hv = __floats2half2_rn(v0 * oscale, v1 * oscale);
                    *(__half2*)&out16[(size_t)m * DMODEL + n0 + ncl] = hv;
                } else {
                    *(float2*)&out32[(size_t)m * DMODEL + n0 + ncl] = make_float2(v0, v1);
                }
            }
        }
    }
}

// merged QKV launch
__global__ __launch_bounds__(256, 2)
void gemm_qkv_kernel(const __half* __restrict__ xf, const __half* __restrict__ wf,
                     const float* __restrict__ b_q, const float* __restrict__ b_k,
                     const float* __restrict__ b_v, const float* __restrict__ tb,
                     const float* __restrict__ u_q, const float* __restrict__ u_k,
                     const float* __restrict__ u_v,
                     __half* __restrict__ qh, __half* __restrict__ kh,
                     __half* __restrict__ vh) {
    const int z = blockIdx.z;
    const __half* Wt = wf + (size_t)z * DMODEL * DMODEL;
    const float* bias = (z == 0) ? b_q : (z == 1) ? b_k : b_v;
    const float* u    = (z == 0) ? u_q : (z == 1) ? u_k : u_v;
    const float* t    = tb + (size_t)z * MTOT * LORA_R;
    __half* out       = (z == 0) ? qh : (z == 1) ? kh : vh;
    const float osc   = (z == 0) ? QSCALE : 1.0f;
    gemm_core(xf, Wt, bias, t, u, nullptr, out, osc,
              blockIdx.y * 128, blockIdx.x * 128);
}

__global__ __launch_bounds__(256, 2)
void gemm_o_kernel(const __half* __restrict__ af, const __half* __restrict__ wf,
                   const float* __restrict__ b_o, float* __restrict__ out) {
    gemm_core(af, wf + 3ULL * DMODEL * DMODEL, b_o, nullptr, nullptr,
              out, nullptr, 1.0f, blockIdx.y * 128, blockIdx.x * 128);
}

// ---------------- kernel 3: flash attention ---------------------------------
// Br=64 (4 warps, 128 threads, occ 4), Bc=32, P in regs, Q frags hoisted,
// 3-stage cp.async K/V, row-sums via ones-mma.  (R13, unchanged)
#define ATS 4096
#define H1X2 0x3C003C00u   // half2(1.0, 1.0)

__global__ __launch_bounds__(128, 4) void attn_kernel() {
    __shared__ __align__(16) __half Qs[64 * 64];        // 8 KB
    __shared__ __align__(16) __half KVs[3][2][32 * 64]; // 24 KB

    const int tid  = threadIdx.x;
    const int warp = tid >> 5;
    const int lane = tid & 31;
    const int g = lane >> 2;
    const int t = lane & 3;
    const int r0 = warp * 16;
    const int q0 = blockIdx.x * 64;
    const int bh = blockIdx.y;
    const int b = bh >> 4, h = bh & 15;

    const __half* qbase = g_qh + (size_t)b * SEQ * DMODEL + h * DK;
    const __half* kbase = g_kh + (size_t)b * SEQ * DMODEL + h * DK;
    const __half* vbase = g_vh + (size_t)b * SEQ * DMODEL + h * DK;

    #pragma unroll
    for (int i = 0; i < 4; i++) {
        int idx = tid + i * 128;
        int row = idx >> 3, c8 = idx & 7;
        uint32_t sw = SMEM_SW(row * 128 + c8 * 16);
        *(uint4*)((char*)Qs + sw) = *(const uint4*)(qbase + (size_t)(q0 + row) * DMODEL + c8 * 8);
    }

    const uint32_t qb = smem_u32(Qs);
    const uint32_t kvb = smem_u32(KVs);

    const int row0s = tid >> 3;
    const int row1s = row0s + 16;
    const int c8s   = tid & 7;
    const uint32_t ssw0 = SMEM_SW(row0s * 128 + c8s * 16);
    const uint32_t ssw1 = SMEM_SW(row1s * 128 + c8s * 16);
    const __half* kp0 = kbase + (size_t)row0s * DMODEL + c8s * 8;
    const __half* kp1 = kbase + (size_t)row1s * DMODEL + c8s * 8;
    const __half* vp0 = vbase + (size_t)row0s * DMODEL + c8s * 8;
    const __half* vp1 = vbase + (size_t)row1s * DMODEL + c8s * 8;

    #define ATT_STAGE(SLOT, TILE) do {                                         \
        const size_t go_ = (size_t)(TILE) * 32 * DMODEL;                       \
        const uint32_t kd_ = kvb + (SLOT) * 2 * ATS;                           \
        cp16(kd_ + ssw0,       kp0 + go_);                                     \
        cp16(kd_ + ssw1,       kp1 + go_);                                     \
        cp16(kd_ + ATS + ssw0, vp0 + go_);                                     \
        cp16(kd_ + ATS + ssw1, vp1 + go_);                                     \
    } while (0)

    ATT_STAGE(0, 0);
    CP_COMMIT();
    ATT_STAGE(1, 1);
    CP_COMMIT();

    uint32_t kfo[4][2];
    #pragma unroll
    for (int ks = 0; ks < 4; ks++)
        #pragma unroll
        for (int ntp = 0; ntp < 2; ntp++)
            kfo[ks][ntp] = SMEM_SW((ntp * 16 + ((lane >> 4) << 3) + (lane & 7)) * 128 +
                                   ((lane >> 3) & 1) * 16 + ks * 32);
    uint32_t vfo[2][4];
    #pragma unroll
    for (int kp_ = 0; kp_ < 2; kp_++)
        #pragma unroll
        for (int ntp = 0; ntp < 4; ntp++)
            vfo[kp_][ntp] = SMEM_SW((kp_ * 16 + ((lane >> 3) & 1) * 8 + (lane & 7)) * 128 +
                                    ntp * 32 + (lane >> 4) * 16);

    __syncthreads();
    unsigned qf[4][4];
    #pragma unroll
    for (int ks = 0; ks < 4; ks++)
        ldsm_x4(qf[ks][0], qf[ks][1], qf[ks][2], qf[ks][3],
                qb + SMEM_SW((r0 + (lane & 15)) * 128 + ks * 32 + (lane >> 4) * 16));

    float O[8][4] = {};
    float rsum[4] = {};

    const int NKV = SEQ / 32;
    for (int tile = 0; tile < NKV; tile++) {
        if (tile + 1 < NKV) { CP_WAIT(1); } else { CP_WAIT(0); }
        __syncthreads();

        if (tile + 2 < NKV) {
            ATT_STAGE((tile + 2) % 3, tile + 2);
            CP_COMMIT();
        }

        const uint32_t kb_t = kvb + (tile % 3) * 2 * ATS;
        const uint32_t vb_t = kb_t + ATS;

        float S[4][4] = {};
        #pragma unroll
        for (int ks = 0; ks < 4; ks++) {
            #pragma unroll
            for (int ntp = 0; ntp < 2; ntp++) {
                unsigned b0, b1, b2, b3;
                ldsm_x4(b0, b1, b2, b3, kb_t + kfo[ks][ntp]);
                mma16h(S[ntp * 2],     qf[ks][0], qf[ks][1], qf[ks][2], qf[ks][3], b0, b1);
                mma16h(S[ntp * 2 + 1], qf[ks][0], qf[ks][1], qf[ks][2], qf[ks][3], b2, b3);
            }
        }

        unsigned ph[8];
        #pragma unroll
        for (int nt = 0; nt < 4; nt++) {
            float p0 = ex2(S[nt][0]), p1 = ex2(S[nt][1]);
            float p2 = ex2(S[nt][2]), p3 = ex2(S[nt][3]);
            __half2 h01 = __floats2half2_rn(p0, p1);
            __half2 h23 = __floats2half2_rn(p2, p3);
            ph[nt * 2]     = *(unsigned*)&h01;
            ph[nt * 2 + 1] = *(unsigned*)&h23;
        }
        mma16h(rsum, ph[0], ph[1], ph[2], ph[3], H1X2, H1X2);
        mma16h(rsum, ph[4], ph[5], ph[6], ph[7], H1X2, H1X2);

        #pragma unroll
        for (int kp_ = 0; kp_ < 2; kp_++) {
            unsigned a0 = ph[kp_ * 4 + 0], a1 = ph[kp_ * 4 + 1];
            unsigned a2 = ph[kp_ * 4 + 2], a3 = ph[kp_ * 4 + 3];
            #pragma unroll
            for (int ntp = 0; ntp < 4; ntp++) {
                unsigned b0, b1, b2, b3;
                ldsm_x4_t(b0, b1, b2, b3, vb_t + vfo[kp_][ntp]);
                mma16h(O[ntp * 2],     a0, a1, a2, a3, b0, b1);
                mma16h(O[ntp * 2 + 1], a0, a1, a2, a3, b2, b3);
            }
        }
    }
    #undef ATT_STAGE

    float inv0 = 1.0f / rsum[0], inv1 = 1.0f / rsum[2];
    const size_t row0 = ((size_t)b * SEQ + q0 + r0 + g) * DMODEL + h * DK;
    const size_t row1 = row0 + 8 * DMODEL;
    #pragma unroll
    for (int nt = 0; nt < 8; nt++) {
        const int c = nt * 8 + 2 * t;
        *(__half2*)&g_af[row0 + c] = __floats2half2_rn(O[nt][0] * inv0, O[nt][1] * inv0);
        *(__half2*)&g_af[row1 + c] = __floats2half2_rn(O[nt][2] * inv1, O[nt][3] * inv1);
    }
}

// ---------------- launch ----------------------------------------------------
extern "C" void kernel_launch(void* const* d_in, const int* in_sizes, int n_in,
                              void* d_out, int out_size) {
    const float* x   = (const float*)d_in[0];
    const float* w_q = (const float*)d_in[1];
    const float* b_q = (const float*)d_in[2];
    const float* w_k = (const float*)d_in[3];
    const float* b_k = (const float*)d_in[4];
    const float* w_v = (const float*)d_in[5];
    const float* b_v = (const float*)d_in[6];
    const float* w_o = (const float*)d_in[7];
    const float* b_o = (const float*)d_in[8];
    const float* a_q = (const float*)d_in[9];
    const float* u_q = (const float*)d_in[10];
    const float* a_k = (const float*)d_in[11];
    const float* u_k = (const float*)d_in[12];
    const float* a_v = (const float*)d_in[13];
    const float* u_v = (const float*)d_in[14];

    float* t_ptr;
    __half *xf, *wf, *af, *qh, *kh, *vh;
    cudaGetSymbolAddress((void**)&t_ptr, g_t);
    cudaGetSymbolAddress((void**)&xf, g_xf);
    cudaGetSymbolAddress((void**)&wf, g_wf);
    cudaGetSymbolAddress((void**)&af, g_af);
    cudaGetSymbolAddress((void**)&qh, g_qh);
    cudaGetSymbolAddress((void**)&kh, g_kh);
    cudaGetSymbolAddress((void**)&vh, g_vh);

    // 0+1) merged prep
    prep_kernel<<<4096 + MTOT / 32, 256>>>(x, w_q, w_k, w_v, w_o, a_q, a_k, a_v);

    // 2) merged QKV projections
    cudaFuncSetAttribute(gemm_qkv_kernel, cudaFuncAttributeMaxDynamicSharedMemorySize, GSMEM);
    cudaFuncSetAttribute(gemm_o_kernel, cudaFuncAttributeMaxDynamicSharedMemorySize, GSMEM);
    dim3 qkv_grid(DMODEL / 128, MTOT / 128, 3);
    gemm_qkv_kernel<<<qkv_grid, 256, GSMEM>>>(xf, wf, b_q, b_k, b_v, t_ptr,
                                              u_q, u_k, u_v, qh, kh, vh);

    // 3) attention (Br=64, occ 4)
    dim3 agrid(SEQ / 64, BATCH * NHEADS);
    attn_kernel<<<agrid, 128>>>();

    // 4) output projection
    dim3 ogrid(DMODEL / 128, MTOT / 128);
    gemm_o_kernel<<<ogrid, 256, GSMEM>>>(af, wf, b_o, (float*)d_out);
}

// round 16
// speedup vs baseline: 1.4735x; 1.0170x over previous
#include <cuda_runtime.h>
#include <cuda_bf16.h>
#include <cuda_fp16.h>
#include <math.h>
#include <stdint.h>

// Problem constants
#define BATCH   4
#define SEQ     2048
#define DMODEL  1024
#define NHEADS  16
#define DK      64
#define LORA_R  8
#define MTOT    (BATCH * SEQ)       // 8192
#define SCALING 2.0f
#define QSCALE  (0.125f * 1.4426950408889634f)   // fold log2(e)/sqrt(dk) into Q

// ---------------- scratch (device globals; no allocations allowed) ----------
__device__ float g_t[3 * MTOT * LORA_R];
__device__ __half g_xf[MTOT * DMODEL];
__device__ __half g_wf[4 * DMODEL * DMODEL];      // W^T fp16: [w][n][k]
__device__ __half g_af[MTOT * DMODEL];
__device__ __half g_qh[MTOT * DMODEL];            // fp16 Q (pre-scaled log2e/8)
__device__ __half g_kh[MTOT * DMODEL];
__device__ __half g_vh[MTOT * DMODEL];

#define SMEM_SW(off) ((off) ^ (((off) >> 3) & 0x70))

__device__ __forceinline__ uint32_t smem_u32(const void* p) {
    uint32_t a;
    asm("{ .reg .u64 t; cvta.to.shared.u64 t, %1; cvt.u32.u64 %0, t; }" : "=r"(a) : "l"(p));
    return a;
}

// ---------------- mma / ldmatrix / cp.async helpers --------------------------
__device__ __forceinline__ void mma16h(float* d, unsigned a0, unsigned a1, unsigned a2,
                                       unsigned a3, unsigned b0, unsigned b1) {
    asm volatile(
        "mma.sync.aligned.m16n8k16.row.col.f32.f16.f16.f32 "
        "{%0,%1,%2,%3}, {%4,%5,%6,%7}, {%8,%9}, {%0,%1,%2,%3};\n"
        : "+f"(d[0]), "+f"(d[1]), "+f"(d[2]), "+f"(d[3])
        : "r"(a0), "r"(a1), "r"(a2), "r"(a3), "r"(b0), "r"(b1));
}
__device__ __forceinline__ void ldsm_x4(unsigned& r0, unsigned& r1, unsigned& r2,
                                        unsigned& r3, uint32_t addr) {
    asm volatile("ldmatrix.sync.aligned.m8n8.x4.shared.b16 {%0,%1,%2,%3}, [%4];"
                 : "=r"(r0), "=r"(r1), "=r"(r2), "=r"(r3) : "r"(addr));
}
__device__ __forceinline__ void ldsm_x4_t(unsigned& r0, unsigned& r1, unsigned& r2,
                                          unsigned& r3, uint32_t addr) {
    asm volatile("ldmatrix.sync.aligned.m8n8.x4.trans.shared.b16 {%0,%1,%2,%3}, [%4];"
                 : "=r"(r0), "=r"(r1), "=r"(r2), "=r"(r3) : "r"(addr));
}
__device__ __forceinline__ void cp16(uint32_t dst, const void* src) {
    asm volatile("cp.async.cg.shared.global [%0], [%1], 16;" :: "r"(dst), "l"(src));
}
#define CP_COMMIT()  asm volatile("cp.async.commit_group;" ::: "memory")
#define CP_WAIT(n)   asm volatile("cp.async.wait_group %0;" :: "n"(n) : "memory")
__device__ __forceinline__ float ex2(float x) {
    float r;
    asm("ex2.approx.f32 %0, %1;" : "=f"(r) : "f"(x));
    return r;
}

// ---------------- kernel 0+1 merged: weight transpose/fp16 + LoRA down ------
__global__ void prep_kernel(const float* __restrict__ x,
                            const float* __restrict__ w0, const float* __restrict__ w1,
                            const float* __restrict__ w2, const float* __restrict__ w3,
                            const float* __restrict__ aq, const float* __restrict__ ak,
                            const float* __restrict__ av) {
    __shared__ float tile[32][33];
    __shared__ float as[3][32][LORA_R];
    const int tid = threadIdx.x;

    if (blockIdx.x < 4096) {
        const int wsel = blockIdx.x >> 10;
        const int rem  = blockIdx.x & 1023;
        const int k0 = (rem >> 5) * 32, n0 = (rem & 31) * 32;
        const float* W = (wsel == 0) ? w0 : (wsel == 1) ? w1 : (wsel == 2) ? w2 : w3;
        const size_t off = (size_t)wsel * DMODEL * DMODEL;
        const int tx = tid & 31, ty = tid >> 5;
        #pragma unroll
        for (int i = 0; i < 4; i++) {
            int r = ty + i * 8;
            tile[r][tx] = W[(size_t)(k0 + r) * DMODEL + n0 + tx];
        }
        __syncthreads();
        #pragma unroll
        for (int i = 0; i < 4; i++) {
            int r = ty + i * 8;
            g_wf[off + (size_t)(n0 + r) * DMODEL + k0 + tx] = __float2half_rn(tile[tx][r]);
        }
    } else {
        const int m0  = (blockIdx.x - 4096) * 32;
        const int row = tid >> 3;
        const int r   = tid & 7;
        float acc0 = 0.f, acc1 = 0.f, acc2 = 0.f;
        for (int k0 = 0; k0 < DMODEL; k0 += 32) {
            #pragma unroll
            for (int idx = tid; idx < 32 * 32; idx += 256) {
                int rr = idx >> 5, kk = idx & 31;
                float v = x[(size_t)(m0 + rr) * DMODEL + k0 + kk];
                tile[rr][kk] = v;
                g_xf[(size_t)(m0 + rr) * DMODEL + k0 + kk] = __float2half_rn(v);
            }
            for (int idx = tid; idx < 3 * 32 * LORA_R; idx += 256) {
                int w = idx >> 8, rem2 = idx & 255;
                int kk = rem2 >> 3, rj = rem2 & 7;
                const float* a = (w == 0) ? aq : ((w == 1) ? ak : av);
                as[w][kk][rj] = a[(size_t)(k0 + kk) * LORA_R + rj];
            }
            __syncthreads();
            #pragma unroll
            for (int kk = 0; kk < 32; kk++) {
                float xv = tile[row][kk];
                acc0 += xv * as[0][kk][r];
                acc1 += xv * as[1][kk][r];
                acc2 += xv * as[2][kk][r];
            }
            __syncthreads();
        }
        const int m = m0 + row;
        g_t[0 * MTOT * LORA_R + m * LORA_R + r] = acc0;
        g_t[1 * MTOT * LORA_R + m * LORA_R + r] = acc1;
        g_t[2 * MTOT * LORA_R + m * LORA_R + r] = acc2;
    }
}

// ---------------- gemm core: fp16, 3-stage cp.async, 256x128 CTA ------------
// 512 threads (16 warps, 4m x 4n of 64x32 warp tiles), BK=64, occ 1.
// 3-stage pipeline (wait(1), depth-2 overlap), 1 barrier/tile.
#define GA_PL 32768                          // A plane: 256 rows x 128B
#define GBUF  49152                          // A + B (16KB) per stage
#define GSMEM (3 * GBUF + LORA_R * 128 * 4)  // 151552

extern __shared__ char gsm[];

__device__ __forceinline__ void gemm_core(
        const __half* __restrict__ A, const __half* __restrict__ Wt,
        const float* __restrict__ bias,
        const float* __restrict__ t, const float* __restrict__ u,
        float* __restrict__ out32, __half* __restrict__ out16,
        float oscale, int m0, int n0) {
    float* Us = (float*)(gsm + 3 * GBUF);

    const int tid  = threadIdx.x;
    const int warp = tid >> 5;
    const int lane = tid & 31;
    const int g  = lane >> 2;
    const int tq = lane & 3;
    const int wm = warp >> 2;       // 0..3
    const int wn = warp & 3;        // 0..3

    if (u != nullptr) {
        #pragma unroll
        for (int p = 0; p < 2; p++) {
            int idx = tid + p * 512;
            Us[idx] = u[(size_t)(idx >> 7) * DMODEL + n0 + (idx & 127)];
        }
    }

    const uint32_t sbase = smem_u32(gsm);

    // A staging: row = tid>>1 (0..255), 4 chunks at c8 = (tid&1)*4 + i
    const int arow = tid >> 1;
    const int ahq  = (tid & 1) * 4;
    const __half* Ap = A + (size_t)(m0 + arow) * DMODEL + ahq * 8;
    const uint32_t a_soff = arow * 128 + ahq * 16;
    // B staging: row = tid>>2 (0..127), 2 chunks at c8 = (tid&3)*2 + j
    const int brow = tid >> 2;
    const int bhq  = (tid & 3) * 2;
    const __half* Bp = Wt + (size_t)(n0 + brow) * DMODEL + bhq * 8;
    const uint32_t b_soff = brow * 128 + bhq * 16;

    #define STAGE(BUF, TILE) do {                                              \
        const int ko_ = (TILE) * 64;                                           \
        const uint32_t sd_ = sbase + (BUF) * GBUF;                             \
        _Pragma("unroll")                                                      \
        for (int i = 0; i < 4; i++)                                            \
            cp16(sd_ + SMEM_SW(a_soff + i * 16), Ap + ko_ + i * 8);            \
        _Pragma("unroll")                                                      \
        for (int j = 0; j < 2; j++)                                            \
            cp16(sd_ + GA_PL + SMEM_SW(b_soff + j * 16), Bp + ko_ + j * 8);    \
    } while (0)

    STAGE(0, 0);
    CP_COMMIT();
    STAGE(1, 1);
    CP_COMMIT();

    // fragment base byte-offsets (pre-swizzle)
    const uint32_t a_base = (wm * 64 + (lane & 15)) * 128 + (lane >> 4) * 16;
    const uint32_t b_base = (wn * 32 + ((lane >> 4) << 3) + (lane & 7)) * 128 +
                            ((lane >> 3) & 1) * 16;

    float D[4][4][4] = {};
    const int NT = DMODEL / 64;   // 16

    for (int tile = 0; tile < NT; tile++) {
        if (tile + 1 < NT) { CP_WAIT(1); } else { CP_WAIT(0); }
        __syncthreads();   // stage `tile` visible; all warps done computing tile-1

        if (tile + 2 < NT) {
            STAGE((tile + 2) % 3, tile + 2);
            CP_COMMIT();
        }

        const uint32_t ab = sbase + (tile % 3) * GBUF;
        const uint32_t bb = ab + GA_PL;

        #pragma unroll
        for (int ks = 0; ks < 4; ks++) {
            unsigned bf[4][2];
            #pragma unroll
            for (int ntp = 0; ntp < 2; ntp++) {
                unsigned b0, b1, b2, b3;
                ldsm_x4(b0, b1, b2, b3,
                        bb + SMEM_SW(b_base + ntp * 2048 + ks * 32));
                bf[ntp * 2][0] = b0; bf[ntp * 2][1] = b1;
                bf[ntp * 2 + 1][0] = b2; bf[ntp * 2 + 1][1] = b3;
            }
            #pragma unroll
            for (int mt = 0; mt < 4; mt++) {
                unsigned a0, a1, a2, a3;
                ldsm_x4(a0, a1, a2, a3,
                        ab + SMEM_SW(a_base + mt * 2048 + ks * 32));
                #pragma unroll
                for (int nt = 0; nt < 4; nt++)
                    mma16h(D[mt][nt], a0, a1, a2, a3, bf[nt][0], bf[nt][1]);
            }
        }
    }
    #undef STAGE

    // ---- epilogue ----
    #pragma unroll
    for (int mt = 0; mt < 4; mt++) {
        #pragma unroll
        for (int half_ = 0; half_ < 2; half_++) {
            const int m = m0 + wm * 64 + mt * 16 + g + half_ * 8;
            float trow[LORA_R];
            if (t != nullptr) {
                float4 t0 = *(const float4*)&t[(size_t)m * LORA_R];
                float4 t1 = *(const float4*)&t[(size_t)m * LORA_R + 4];
                trow[0] = t0.x; trow[1] = t0.y; trow[2] = t0.z; trow[3] = t0.w;
                trow[4] = t1.x; trow[5] = t1.y; trow[6] = t1.z; trow[7] = t1.w;
            }
            #pragma unroll
            for (int nt = 0; nt < 4; nt++) {
                const int ncl = wn * 32 + nt * 8 + 2 * tq;
                float v0 = D[mt][nt][half_ * 2 + 0] + bias[n0 + ncl];
                float v1 = D[mt][nt][half_ * 2 + 1] + bias[n0 + ncl + 1];
                if (t != nullptr) {
                    float l0 = 0.f, l1 = 0.f;
                    #pragma unroll
                    for (int r = 0; r < LORA_R; r++) {
                        l0 += trow[r] * Us[r * 128 + ncl];
                        l1 += trow[r] * Us[r * 128 + ncl + 1];
                    }
                    v0 += SCALING * l0;
                    v1 += SCALING * l1;
                }
                if (out16 != nullptr) {
                    __half2 hv = __floats2half2_rn(v0 * oscale, v1 * oscale);
                    *(__half2*)&out16[(size_t)m * DMODEL + n0 + ncl] = hv;
                } else {
                    *(float2*)&out32[(size_t)m * DMODEL + n0 + ncl] = make_float2(v0, v1);
                }
            }
        }
    }
}

// merged QKV launch
__global__ __launch_bounds__(512, 1)
void gemm_qkv_kernel(const __half* __restrict__ xf, const __half* __restrict__ wf,
                     const float* __restrict__ b_q, const float* __restrict__ b_k,
                     const float* __restrict__ b_v, const float* __restrict__ tb,
                     const float* __restrict__ u_q, const float* __restrict__ u_k,
                     const float* __restrict__ u_v,
                     __half* __restrict__ qh, __half* __restrict__ kh,
                     __half* __restrict__ vh) {
    const int z = blockIdx.z;
    const __half* Wt = wf + (size_t)z * DMODEL * DMODEL;
    const float* bias = (z == 0) ? b_q : (z == 1) ? b_k : b_v;
    const float* u    = (z == 0) ? u_q : (z == 1) ? u_k : u_v;
    const float* t    = tb + (size_t)z * MTOT * LORA_R;
    __half* out       = (z == 0) ? qh : (z == 1) ? kh : vh;
    const float osc   = (z == 0) ? QSCALE : 1.0f;
    gemm_core(xf, Wt, bias, t, u, nullptr, out, osc,
              blockIdx.y * 256, blockIdx.x * 128);
}

__global__ __launch_bounds__(512, 1)
void gemm_o_kernel(const __half* __restrict__ af, const __half* __restrict__ wf,
                   const float* __restrict__ b_o, float* __restrict__ out) {
    gemm_core(af, wf + 3ULL * DMODEL * DMODEL, b_o, nullptr, nullptr,
              out, nullptr, 1.0f, blockIdx.y * 256, blockIdx.x * 128);
}

// ---------------- kernel 3: flash attention (R13/R15, unchanged) -------------
#define ATS 4096
#define H1X2 0x3C003C00u   // half2(1.0, 1.0)

__global__ __launch_bounds__(128, 4) void attn_kernel() {
    __shared__ __align__(16) __half Qs[64 * 64];
    __shared__ __align__(16) __half KVs[3][2][32 * 64];

    const int tid  = threadIdx.x;
    const int warp = tid >> 5;
    const int lane = tid & 31;
    const int g = lane >> 2;
    const int t = lane & 3;
    const int r0 = warp * 16;
    const int q0 = blockIdx.x * 64;
    const int bh = blockIdx.y;
    const int b = bh >> 4, h = bh & 15;

    const __half* qbase = g_qh + (size_t)b * SEQ * DMODEL + h * DK;
    const __half* kbase = g_kh + (size_t)b * SEQ * DMODEL + h * DK;
    const __half* vbase = g_vh + (size_t)b * SEQ * DMODEL + h * DK;

    #pragma unroll
    for (int i = 0; i < 4; i++) {
        int idx = tid + i * 128;
        int row = idx >> 3, c8 = idx & 7;
        uint32_t sw = SMEM_SW(row * 128 + c8 * 16);
        *(uint4*)((char*)Qs + sw) = *(const uint4*)(qbase + (size_t)(q0 + row) * DMODEL + c8 * 8);
    }

    const uint32_t qb = smem_u32(Qs);
    const uint32_t kvb = smem_u32(KVs);

    const int row0s = tid >> 3;
    const int row1s = row0s + 16;
    const int c8s   = tid & 7;
    const uint32_t ssw0 = SMEM_SW(row0s * 128 + c8s * 16);
    const uint32_t ssw1 = SMEM_SW(row1s * 128 + c8s * 16);
    const __half* kp0 = kbase + (size_t)row0s * DMODEL + c8s * 8;
    const __half* kp1 = kbase + (size_t)row1s * DMODEL + c8s * 8;
    const __half* vp0 = vbase + (size_t)row0s * DMODEL + c8s * 8;
    const __half* vp1 = vbase + (size_t)row1s * DMODEL + c8s * 8;

    #define ATT_STAGE(SLOT, TILE) do {                                         \
        const size_t go_ = (size_t)(TILE) * 32 * DMODEL;                       \
        const uint32_t kd_ = kvb + (SLOT) * 2 * ATS;                           \
        cp16(kd_ + ssw0,       kp0 + go_);                                     \
        cp16(kd_ + ssw1,       kp1 + go_);                                     \
        cp16(kd_ + ATS + ssw0, vp0 + go_);                                     \
        cp16(kd_ + ATS + ssw1, vp1 + go_);                                     \
    } while (0)

    ATT_STAGE(0, 0);
    CP_COMMIT();
    ATT_STAGE(1, 1);
    CP_COMMIT();

    uint32_t kfo[4][2];
    #pragma unroll
    for (int ks = 0; ks < 4; ks++)
        #pragma unroll
        for (int ntp = 0; ntp < 2; ntp++)
            kfo[ks][ntp] = SMEM_SW((ntp * 16 + ((lane >> 4) << 3) + (lane & 7)) * 128 +
                                   ((lane >> 3) & 1) * 16 + ks * 32);
    uint32_t vfo[2][4];
    #pragma unroll
    for (int kp_ = 0; kp_ < 2; kp_++)
        #pragma unroll
        for (int ntp = 0; ntp < 4; ntp++)
            vfo[kp_][ntp] = SMEM_SW((kp_ * 16 + ((lane >> 3) & 1) * 8 + (lane & 7)) * 128 +
                                    ntp * 32 + (lane >> 4) * 16);

    __syncthreads();
    unsigned qf[4][4];
    #pragma unroll
    for (int ks = 0; ks < 4; ks++)
        ldsm_x4(qf[ks][0], qf[ks][1], qf[ks][2], qf[ks][3],
                qb + SMEM_SW((r0 + (lane & 15)) * 128 + ks * 32 + (lane >> 4) * 16));

    float O[8][4] = {};
    float rsum[4] = {};

    const int NKV = SEQ / 32;
    for (int tile = 0; tile < NKV; tile++) {
        if (tile + 1 < NKV) { CP_WAIT(1); } else { CP_WAIT(0); }
        __syncthreads();

        if (tile + 2 < NKV) {
            ATT_STAGE((tile + 2) % 3, tile + 2);
            CP_COMMIT();
        }

        const uint32_t kb_t = kvb + (tile % 3) * 2 * ATS;
        const uint32_t vb_t = kb_t + ATS;

        float S[4][4] = {};
        #pragma unroll
        for (int ks = 0; ks < 4; ks++) {
            #pragma unroll
            for (int ntp = 0; ntp < 2; ntp++) {
                unsigned b0, b1, b2, b3;
                ldsm_x4(b0, b1, b2, b3, kb_t + kfo[ks][ntp]);
                mma16h(S[ntp * 2],     qf[ks][0], qf[ks][1], qf[ks][2], qf[ks][3], b0, b1);
                mma16h(S[ntp * 2 + 1], qf[ks][0], qf[ks][1], qf[ks][2], qf[ks][3], b2, b3);
            }
        }

        unsigned ph[8];
        #pragma unroll
        for (int nt = 0; nt < 4; nt++) {
            float p0 = ex2(S[nt][0]), p1 = ex2(S[nt][1]);
            float p2 = ex2(S[nt][2]), p3 = ex2(S[nt][3]);
            __half2 h01 = __floats2half2_rn(p0, p1);
            __half2 h23 = __floats2half2_rn(p2, p3);
            ph[nt * 2]     = *(unsigned*)&h01;
            ph[nt * 2 + 1] = *(unsigned*)&h23;
        }
        mma16h(rsum, ph[0], ph[1], ph[2], ph[3], H1X2, H1X2);
        mma16h(rsum, ph[4], ph[5], ph[6], ph[7], H1X2, H1X2);

        #pragma unroll
        for (int kp_ = 0; kp_ < 2; kp_++) {
            unsigned a0 = ph[kp_ * 4 + 0], a1 = ph[kp_ * 4 + 1];
            unsigned a2 = ph[kp_ * 4 + 2], a3 = ph[kp_ * 4 + 3];
            #pragma unroll
            for (int ntp = 0; ntp < 4; ntp++) {
                unsigned b0, b1, b2, b3;
                ldsm_x4_t(b0, b1, b2, b3, vb_t + vfo[kp_][ntp]);
                mma16h(O[ntp * 2],     a0, a1, a2, a3, b0, b1);
                mma16h(O[ntp * 2 + 1], a0, a1, a2, a3, b2, b3);
            }
        }
    }
    #undef ATT_STAGE

    float inv0 = 1.0f / rsum[0], inv1 = 1.0f / rsum[2];
    const size_t row0 = ((size_t)b * SEQ + q0 + r0 + g) * DMODEL + h * DK;
    const size_t row1 = row0 + 8 * DMODEL;
    #pragma unroll
    for (int nt = 0; nt < 8; nt++) {
        const int c = nt * 8 + 2 * t;
        *(__half2*)&g_af[row0 + c] = __floats2half2_rn(O[nt][0] * inv0, O[nt][1] * inv0);
        *(__half2*)&g_af[row1 + c] = __floats2half2_rn(O[nt][2] * inv1, O[nt][3] * inv1);
    }
}

// ---------------- launch ----------------------------------------------------
extern "C" void kernel_launch(void* const* d_in, const int* in_sizes, int n_in,
                              void* d_out, int out_size) {
    const float* x   = (const float*)d_in[0];
    const float* w_q = (const float*)d_in[1];
    const float* b_q = (const float*)d_in[2];
    const float* w_k = (const float*)d_in[3];
    const float* b_k = (const float*)d_in[4];
    const float* w_v = (const float*)d_in[5];
    const float* b_v = (const float*)d_in[6];
    const float* w_o = (const float*)d_in[7];
    const float* b_o = (const float*)d_in[8];
    const float* a_q = (const float*)d_in[9];
    const float* u_q = (const float*)d_in[10];
    const float* a_k = (const float*)d_in[11];
    const float* u_k = (const float*)d_in[12];
    const float* a_v = (const float*)d_in[13];
    const float* u_v = (const float*)d_in[14];

    float* t_ptr;
    __half *xf, *wf, *af, *qh, *kh, *vh;
    cudaGetSymbolAddress((void**)&t_ptr, g_t);
    cudaGetSymbolAddress((void**)&xf, g_xf);
    cudaGetSymbolAddress((void**)&wf, g_wf);
    cudaGetSymbolAddress((void**)&af, g_af);
    cudaGetSymbolAddress((void**)&qh, g_qh);
    cudaGetSymbolAddress((void**)&kh, g_kh);
    cudaGetSymbolAddress((void**)&vh, g_vh);

    // 0+1) merged prep
    prep_kernel<<<4096 + MTOT / 32, 256>>>(x, w_q, w_k, w_v, w_o, a_q, a_k, a_v);

    // 2) merged QKV projections (256x128 CTAs, 512 threads)
    cudaFuncSetAttribute(gemm_qkv_kernel, cudaFuncAttributeMaxDynamicSharedMemorySize, GSMEM);
    cudaFuncSetAttribute(gemm_o_kernel, cudaFuncAttributeMaxDynamicSharedMemorySize, GSMEM);
    dim3 qkv_grid(DMODEL / 128, MTOT / 256, 3);
    gemm_qkv_kernel<<<qkv_grid, 512, GSMEM>>>(xf, wf, b_q, b_k, b_v, t_ptr,
                                              u_q, u_k, u_v, qh, kh, vh);

    // 3) attention (Br=64, occ 4)
    dim3 agrid(SEQ / 64, BATCH * NHEADS);
    attn_kernel<<<agrid, 128>>>();

    // 4) output projection
    dim3 ogrid(DMODEL / 128, MTOT / 256);
    gemm_o_kernel<<<ogrid, 512, GSMEM>>>(af, wf, b_o, (float*)d_out);
}

// round 17
// speedup vs baseline: 1.4900x; 1.0112x over previous
#include <cuda_runtime.h>
#include <cuda_bf16.h>
#include <cuda_fp16.h>
#include <math.h>
#include <stdint.h>

// Problem constants
#define BATCH   4
#define SEQ     2048
#define DMODEL  1024
#define NHEADS  16
#define DK      64
#define LORA_R  8
#define MTOT    (BATCH * SEQ)       // 8192
#define SCALING 2.0f
#define QSCALE  (0.125f * 1.4426950408889634f)   // fold log2(e)/sqrt(dk) into Q

// ---------------- scratch (device globals; no allocations allowed) ----------
__device__ float g_t[3 * MTOT * LORA_R];
__device__ __half g_xf[MTOT * DMODEL];
__device__ __half g_wf[4 * DMODEL * DMODEL];      // W^T fp16: [w][n][k]
__device__ __half g_af[MTOT * DMODEL];
__device__ __half g_qh[MTOT * DMODEL];            // fp16 Q (pre-scaled log2e/8)
__device__ __half g_kh[MTOT * DMODEL];
__device__ __half g_vh[MTOT * DMODEL];

#define SMEM_SW(off) ((off) ^ (((off) >> 3) & 0x70))

__device__ __forceinline__ uint32_t smem_u32(const void* p) {
    uint32_t a;
    asm("{ .reg .u64 t; cvta.to.shared.u64 t, %1; cvt.u32.u64 %0, t; }" : "=r"(a) : "l"(p));
    return a;
}

// ---------------- mma / ldmatrix / cp.async helpers --------------------------
__device__ __forceinline__ void mma16h(float* d, unsigned a0, unsigned a1, unsigned a2,
                                       unsigned a3, unsigned b0, unsigned b1) {
    asm volatile(
        "mma.sync.aligned.m16n8k16.row.col.f32.f16.f16.f32 "
        "{%0,%1,%2,%3}, {%4,%5,%6,%7}, {%8,%9}, {%0,%1,%2,%3};\n"
        : "+f"(d[0]), "+f"(d[1]), "+f"(d[2]), "+f"(d[3])
        : "r"(a0), "r"(a1), "r"(a2), "r"(a3), "r"(b0), "r"(b1));
}
__device__ __forceinline__ void ldsm_x4(unsigned& r0, unsigned& r1, unsigned& r2,
                                        unsigned& r3, uint32_t addr) {
    asm volatile("ldmatrix.sync.aligned.m8n8.x4.shared.b16 {%0,%1,%2,%3}, [%4];"
                 : "=r"(r0), "=r"(r1), "=r"(r2), "=r"(r3) : "r"(addr));
}
__device__ __forceinline__ void ldsm_x4_t(unsigned& r0, unsigned& r1, unsigned& r2,
                                          unsigned& r3, uint32_t addr) {
    asm volatile("ldmatrix.sync.aligned.m8n8.x4.trans.shared.b16 {%0,%1,%2,%3}, [%4];"
                 : "=r"(r0), "=r"(r1), "=r"(r2), "=r"(r3) : "r"(addr));
}
__device__ __forceinline__ void cp16(uint32_t dst, const void* src) {
    asm volatile("cp.async.cg.shared.global [%0], [%1], 16;" :: "r"(dst), "l"(src));
}
#define CP_COMMIT()  asm volatile("cp.async.commit_group;" ::: "memory")
#define CP_WAIT(n)   asm volatile("cp.async.wait_group %0;" :: "n"(n) : "memory")
__device__ __forceinline__ float ex2(float x) {
    float r;
    asm("ex2.approx.f32 %0, %1;" : "=f"(r) : "f"(x));
    return r;
}

// ---------------- kernel 0+1 merged: weight transpose/fp16 + LoRA down ------
__global__ void prep_kernel(const float* __restrict__ x,
                            const float* __restrict__ w0, const float* __restrict__ w1,
                            const float* __restrict__ w2, const float* __restrict__ w3,
                            const float* __restrict__ aq, const float* __restrict__ ak,
                            const float* __restrict__ av) {
    __shared__ float tile[32][33];
    __shared__ float as[3][32][LORA_R];
    const int tid = threadIdx.x;

    if (blockIdx.x < 4096) {
        const int wsel = blockIdx.x >> 10;
        const int rem  = blockIdx.x & 1023;
        const int k0 = (rem >> 5) * 32, n0 = (rem & 31) * 32;
        const float* W = (wsel == 0) ? w0 : (wsel == 1) ? w1 : (wsel == 2) ? w2 : w3;
        const size_t off = (size_t)wsel * DMODEL * DMODEL;
        const int tx = tid & 31, ty = tid >> 5;
        #pragma unroll
        for (int i = 0; i < 4; i++) {
            int r = ty + i * 8;
            tile[r][tx] = W[(size_t)(k0 + r) * DMODEL + n0 + tx];
        }
        __syncthreads();
        #pragma unroll
        for (int i = 0; i < 4; i++) {
            int r = ty + i * 8;
            g_wf[off + (size_t)(n0 + r) * DMODEL + k0 + tx] = __float2half_rn(tile[tx][r]);
        }
    } else {
        const int m0  = (blockIdx.x - 4096) * 32;
        const int row = tid >> 3;
        const int r   = tid & 7;
        float acc0 = 0.f, acc1 = 0.f, acc2 = 0.f;
        for (int k0 = 0; k0 < DMODEL; k0 += 32) {
            #pragma unroll
            for (int idx = tid; idx < 32 * 32; idx += 256) {
                int rr = idx >> 5, kk = idx & 31;
                float v = x[(size_t)(m0 + rr) * DMODEL + k0 + kk];
                tile[rr][kk] = v;
                g_xf[(size_t)(m0 + rr) * DMODEL + k0 + kk] = __float2half_rn(v);
            }
            for (int idx = tid; idx < 3 * 32 * LORA_R; idx += 256) {
                int w = idx >> 8, rem2 = idx & 255;
                int kk = rem2 >> 3, rj = rem2 & 7;
                const float* a = (w == 0) ? aq : ((w == 1) ? ak : av);
                as[w][kk][rj] = a[(size_t)(k0 + kk) * LORA_R + rj];
            }
            __syncthreads();
            #pragma unroll
            for (int kk = 0; kk < 32; kk++) {
                float xv = tile[row][kk];
                acc0 += xv * as[0][kk][r];
                acc1 += xv * as[1][kk][r];
                acc2 += xv * as[2][kk][r];
            }
            __syncthreads();
        }
        const int m = m0 + row;
        g_t[0 * MTOT * LORA_R + m * LORA_R + r] = acc0;
        g_t[1 * MTOT * LORA_R + m * LORA_R + r] = acc1;
        g_t[2 * MTOT * LORA_R + m * LORA_R + r] = acc2;
    }
}

// ---------------- gemm core: fp16, 3-stage cp.async, 256x128 CTA (R16) ------
#define GA_PL 32768                          // A plane: 256 rows x 128B
#define GBUF  49152                          // A + B (16KB) per stage
#define GSMEM (3 * GBUF + LORA_R * 128 * 4)  // 151552

extern __shared__ char gsm[];

__device__ __forceinline__ void gemm_core(
        const __half* __restrict__ A, const __half* __restrict__ Wt,
        const float* __restrict__ bias,
        const float* __restrict__ t, const float* __restrict__ u,
        float* __restrict__ out32, __half* __restrict__ out16,
        float oscale, int m0, int n0) {
    float* Us = (float*)(gsm + 3 * GBUF);

    const int tid  = threadIdx.x;
    const int warp = tid >> 5;
    const int lane = tid & 31;
    const int g  = lane >> 2;
    const int tq = lane & 3;
    const int wm = warp >> 2;       // 0..3
    const int wn = warp & 3;        // 0..3

    if (u != nullptr) {
        #pragma unroll
        for (int p = 0; p < 2; p++) {
            int idx = tid + p * 512;
            Us[idx] = u[(size_t)(idx >> 7) * DMODEL + n0 + (idx & 127)];
        }
    }

    const uint32_t sbase = smem_u32(gsm);

    const int arow = tid >> 1;
    const int ahq  = (tid & 1) * 4;
    const __half* Ap = A + (size_t)(m0 + arow) * DMODEL + ahq * 8;
    const uint32_t a_soff = arow * 128 + ahq * 16;
    const int brow = tid >> 2;
    const int bhq  = (tid & 3) * 2;
    const __half* Bp = Wt + (size_t)(n0 + brow) * DMODEL + bhq * 8;
    const uint32_t b_soff = brow * 128 + bhq * 16;

    #define STAGE(BUF, TILE) do {                                              \
        const int ko_ = (TILE) * 64;                                           \
        const uint32_t sd_ = sbase + (BUF) * GBUF;                             \
        _Pragma("unroll")                                                      \
        for (int i = 0; i < 4; i++)                                            \
            cp16(sd_ + SMEM_SW(a_soff + i * 16), Ap + ko_ + i * 8);            \
        _Pragma("unroll")                                                      \
        for (int j = 0; j < 2; j++)                                            \
            cp16(sd_ + GA_PL + SMEM_SW(b_soff + j * 16), Bp + ko_ + j * 8);    \
    } while (0)

    STAGE(0, 0);
    CP_COMMIT();
    STAGE(1, 1);
    CP_COMMIT();

    const uint32_t a_base = (wm * 64 + (lane & 15)) * 128 + (lane >> 4) * 16;
    const uint32_t b_base = (wn * 32 + ((lane >> 4) << 3) + (lane & 7)) * 128 +
                            ((lane >> 3) & 1) * 16;

    float D[4][4][4] = {};
    const int NT = DMODEL / 64;   // 16

    for (int tile = 0; tile < NT; tile++) {
        if (tile + 1 < NT) { CP_WAIT(1); } else { CP_WAIT(0); }
        __syncthreads();

        if (tile + 2 < NT) {
            STAGE((tile + 2) % 3, tile + 2);
            CP_COMMIT();
        }

        const uint32_t ab = sbase + (tile % 3) * GBUF;
        const uint32_t bb = ab + GA_PL;

        #pragma unroll
        for (int ks = 0; ks < 4; ks++) {
            unsigned bf[4][2];
            #pragma unroll
            for (int ntp = 0; ntp < 2; ntp++) {
                unsigned b0, b1, b2, b3;
                ldsm_x4(b0, b1, b2, b3,
                        bb + SMEM_SW(b_base + ntp * 2048 + ks * 32));
                bf[ntp * 2][0] = b0; bf[ntp * 2][1] = b1;
                bf[ntp * 2 + 1][0] = b2; bf[ntp * 2 + 1][1] = b3;
            }
            #pragma unroll
            for (int mt = 0; mt < 4; mt++) {
                unsigned a0, a1, a2, a3;
                ldsm_x4(a0, a1, a2, a3,
                        ab + SMEM_SW(a_base + mt * 2048 + ks * 32));
                #pragma unroll
                for (int nt = 0; nt < 4; nt++)
                    mma16h(D[mt][nt], a0, a1, a2, a3, bf[nt][0], bf[nt][1]);
            }
        }
    }
    #undef STAGE

    // ---- epilogue ----
    #pragma unroll
    for (int mt = 0; mt < 4; mt++) {
        #pragma unroll
        for (int half_ = 0; half_ < 2; half_++) {
            const int m = m0 + wm * 64 + mt * 16 + g + half_ * 8;
            float trow[LORA_R];
            if (t != nullptr) {
                float4 t0 = *(const float4*)&t[(size_t)m * LORA_R];
                float4 t1 = *(const float4*)&t[(size_t)m * LORA_R + 4];
                trow[0] = t0.x; trow[1] = t0.y; trow[2] = t0.z; trow[3] = t0.w;
                trow[4] = t1.x; trow[5] = t1.y; trow[6] = t1.z; trow[7] = t1.w;
            }
            #pragma unroll
            for (int nt = 0; nt < 4; nt++) {
                const int ncl = wn * 32 + nt * 8 + 2 * tq;
                float v0 = D[mt][nt][half_ * 2 + 0] + bias[n0 + ncl];
                float v1 = D[mt][nt][half_ * 2 + 1] + bias[n0 + ncl + 1];
                if (t != nullptr) {
                    float l0 = 0.f, l1 = 0.f;
                    #pragma unroll
                    for (int r = 0; r < LORA_R; r++) {
                        l0 += trow[r] * Us[r * 128 + ncl];
                        l1 += trow[r] * Us[r * 128 + ncl + 1];
                    }
                    v0 += SCALING * l0;
                    v1 += SCALING * l1;
                }
                if (out16 != nullptr) {
                    __half2 hv = __floats2half2_rn(v0 * oscale, v1 * oscale);
                    *(__half2*)&out16[(size_t)m * DMODEL + n0 + ncl] = hv;
                } else {
                    *(float2*)&out32[(size_t)m * DMODEL + n0 + ncl] = make_float2(v0, v1);
                }
            }
        }
    }
}

// merged QKV launch
__global__ __launch_bounds__(512, 1)
void gemm_qkv_kernel(const __half* __restrict__ xf, const __half* __restrict__ wf,
                     const float* __restrict__ b_q, const float* __restrict__ b_k,
                     const float* __restrict__ b_v, const float* __restrict__ tb,
                     const float* __restrict__ u_q, const float* __restrict__ u_k,
                     const float* __restrict__ u_v,
                     __half* __restrict__ qh, __half* __restrict__ kh,
                     __half* __restrict__ vh) {
    const int z = blockIdx.z;
    const __half* Wt = wf + (size_t)z * DMODEL * DMODEL;
    const float* bias = (z == 0) ? b_q : (z == 1) ? b_k : b_v;
    const float* u    = (z == 0) ? u_q : (z == 1) ? u_k : u_v;
    const float* t    = tb + (size_t)z * MTOT * LORA_R;
    __half* out       = (z == 0) ? qh : (z == 1) ? kh : vh;
    const float osc   = (z == 0) ? QSCALE : 1.0f;
    gemm_core(xf, Wt, bias, t, u, nullptr, out, osc,
              blockIdx.y * 256, blockIdx.x * 128);
}

__global__ __launch_bounds__(512, 1)
void gemm_o_kernel(const __half* __restrict__ af, const __half* __restrict__ wf,
                   const float* __restrict__ b_o, float* __restrict__ out) {
    gemm_core(af, wf + 3ULL * DMODEL * DMODEL, b_o, nullptr, nullptr,
              out, nullptr, 1.0f, blockIdx.y * 256, blockIdx.x * 128);
}

// ---------------- kernel 3: flash attention ---------------------------------
// Br=64 (4 warps, 128 threads, occ 4), Bc=32, P in regs, Q frags hoisted.
// 6-slot cp.async K/V ring, TWO tiles per iteration, 1 barrier per 2 tiles.
#define ATS 4096
#define H1X2 0x3C003C00u   // half2(1.0, 1.0)

__global__ __launch_bounds__(128, 4) void attn_kernel() {
    __shared__ __align__(16) __half Qs[64 * 64];        // 8 KB
    __shared__ __align__(16) __half KVs[6][2][32 * 64]; // 48 KB (6-slot ring)

    const int tid  = threadIdx.x;
    const int warp = tid >> 5;
    const int lane = tid & 31;
    const int g = lane >> 2;
    const int t = lane & 3;
    const int r0 = warp * 16;
    const int q0 = blockIdx.x * 64;
    const int bh = blockIdx.y;
    const int b = bh >> 4, h = bh & 15;

    const __half* qbase = g_qh + (size_t)b * SEQ * DMODEL + h * DK;
    const __half* kbase = g_kh + (size_t)b * SEQ * DMODEL + h * DK;
    const __half* vbase = g_vh + (size_t)b * SEQ * DMODEL + h * DK;

    #pragma unroll
    for (int i = 0; i < 4; i++) {
        int idx = tid + i * 128;
        int row = idx >> 3, c8 = idx & 7;
        uint32_t sw = SMEM_SW(row * 128 + c8 * 16);
        *(uint4*)((char*)Qs + sw) = *(const uint4*)(qbase + (size_t)(q0 + row) * DMODEL + c8 * 8);
    }

    const uint32_t qb = smem_u32(Qs);
    const uint32_t kvb = smem_u32(KVs);

    const int row0s = tid >> 3;
    const int row1s = row0s + 16;
    const int c8s   = tid & 7;
    const uint32_t ssw0 = SMEM_SW(row0s * 128 + c8s * 16);
    const uint32_t ssw1 = SMEM_SW(row1s * 128 + c8s * 16);
    const __half* kp0 = kbase + (size_t)row0s * DMODEL + c8s * 8;
    const __half* kp1 = kbase + (size_t)row1s * DMODEL + c8s * 8;
    const __half* vp0 = vbase + (size_t)row0s * DMODEL + c8s * 8;
    const __half* vp1 = vbase + (size_t)row1s * DMODEL + c8s * 8;

    #define ATT_STAGE(SLOT, TILE) do {                                         \
        const size_t go_ = (size_t)(TILE) * 32 * DMODEL;                       \
        const uint32_t kd_ = kvb + (SLOT) * 2 * ATS;                           \
        cp16(kd_ + ssw0,       kp0 + go_);                                     \
        cp16(kd_ + ssw1,       kp1 + go_);                                     \
        cp16(kd_ + ATS + ssw0, vp0 + go_);                                     \
        cp16(kd_ + ATS + ssw1, vp1 + go_);                                     \
    } while (0)

    // prologue: group0 = tiles {0,1}, group1 = tiles {2,3}
    ATT_STAGE(0, 0);
    ATT_STAGE(1, 1);
    CP_COMMIT();
    ATT_STAGE(2, 2);
    ATT_STAGE(3, 3);
    CP_COMMIT();

    uint32_t kfo[4][2];
    #pragma unroll
    for (int ks = 0; ks < 4; ks++)
        #pragma unroll
        for (int ntp = 0; ntp < 2; ntp++)
            kfo[ks][ntp] = SMEM_SW((ntp * 16 + ((lane >> 4) << 3) + (lane & 7)) * 128 +
                                   ((lane >> 3) & 1) * 16 + ks * 32);
    uint32_t vfo[2][4];
    #pragma unroll
    for (int kp_ = 0; kp_ < 2; kp_++)
        #pragma unroll
        for (int ntp = 0; ntp < 4; ntp++)
            vfo[kp_][ntp] = SMEM_SW((kp_ * 16 + ((lane >> 3) & 1) * 8 + (lane & 7)) * 128 +
                                    ntp * 32 + (lane >> 4) * 16);

    __syncthreads();
    unsigned qf[4][4];
    #pragma unroll
    for (int ks = 0; ks < 4; ks++)
        ldsm_x4(qf[ks][0], qf[ks][1], qf[ks][2], qf[ks][3],
                qb + SMEM_SW((r0 + (lane & 15)) * 128 + ks * 32 + (lane >> 4) * 16));

    float O[8][4] = {};
    float rsum[4] = {};

    // one tile's worth of compute (slot base passed in)
    #define ATT_COMPUTE(SLOT) do {                                             \
        const uint32_t kb_t = kvb + (SLOT) * 2 * ATS;                          \
        const uint32_t vb_t = kb_t + ATS;                                      \
        float S[4][4] = {};                                                    \
        _Pragma("unroll")                                                      \
        for (int ks = 0; ks < 4; ks++) {                                       \
            _Pragma("unroll")                                                  \
            for (int ntp = 0; ntp < 2; ntp++) {                                \
                unsigned b0, b1, b2, b3;                                       \
                ldsm_x4(b0, b1, b2, b3, kb_t + kfo[ks][ntp]);                  \
                mma16h(S[ntp * 2],     qf[ks][0], qf[ks][1], qf[ks][2],        \
                       qf[ks][3], b0, b1);                                     \
                mma16h(S[ntp * 2 + 1], qf[ks][0], qf[ks][1], qf[ks][2],        \
                       qf[ks][3], b2, b3);                                     \
            }                                                                  \
        }                                                                      \
        unsigned ph[8];                                                        \
        _Pragma("unroll")                                                      \
        for (int nt = 0; nt < 4; nt++) {                                       \
            float p0 = ex2(S[nt][0]), p1 = ex2(S[nt][1]);                      \
            float p2 = ex2(S[nt][2]), p3 = ex2(S[nt][3]);                      \
            __half2 h01 = __floats2half2_rn(p0, p1);                           \
            __half2 h23 = __floats2half2_rn(p2, p3);                           \
            ph[nt * 2]     = *(unsigned*)&h01;                                 \
            ph[nt * 2 + 1] = *(unsigned*)&h23;                                 \
        }                                                                      \
        mma16h(rsum, ph[0], ph[1], ph[2], ph[3], H1X2, H1X2);                  \
        mma16h(rsum, ph[4], ph[5], ph[6], ph[7], H1X2, H1X2);                  \
        _Pragma("unroll")                                                      \
        for (int kp_ = 0; kp_ < 2; kp_++) {                                    \
            unsigned a0 = ph[kp_ * 4 + 0], a1 = ph[kp_ * 4 + 1];               \
            unsigned a2 = ph[kp_ * 4 + 2], a3 = ph[kp_ * 4 + 3];               \
            _Pragma("unroll")                                                  \
            for (int ntp = 0; ntp < 4; ntp++) {                                \
                unsigned b0, b1, b2, b3;                                       \
                ldsm_x4_t(b0, b1, b2, b3, vb_t + vfo[kp_][ntp]);               \
                mma16h(O[ntp * 2],     a0, a1, a2, a3, b0, b1);                \
                mma16h(O[ntp * 2 + 1], a0, a1, a2, a3, b2, b3);                \
            }                                                                  \
        }                                                                      \
    } while (0)

    const int NIT = SEQ / 64;   // 32 iterations, 2 tiles each
    for (int it = 0; it < NIT; it++) {
        const int t0 = it * 2;
        if (t0 + 2 < SEQ / 32) { CP_WAIT(1); } else { CP_WAIT(0); }
        __syncthreads();   // group {t0,t0+1} visible; all warps past iter it-1

        // stage tiles t0+4, t0+5 into slots (t0+4)%6, (t0+5)%6
        // (slots t0..t0+5 mod 6 are 6 consecutive -> all distinct; the
        //  overwritten slots held tiles t0-2,t0-1, finished last iter,
        //  protected by the sync above)
        if (t0 + 4 < SEQ / 32) {
            ATT_STAGE((t0 + 4) % 6, t0 + 4);
            ATT_STAGE((t0 + 5) % 6, t0 + 5);
            CP_COMMIT();
        }

        ATT_COMPUTE(t0 % 6);
        ATT_COMPUTE((t0 + 1) % 6);
    }
    #undef ATT_COMPUTE
    #undef ATT_STAGE

    float inv0 = 1.0f / rsum[0], inv1 = 1.0f / rsum[2];
    const size_t row0 = ((size_t)b * SEQ + q0 + r0 + g) * DMODEL + h * DK;
    const size_t row1 = row0 + 8 * DMODEL;
    #pragma unroll
    for (int nt = 0; nt < 8; nt++) {
        const int c = nt * 8 + 2 * t;
        *(__half2*)&g_af[row0 + c] = __floats2half2_rn(O[nt][0] * inv0, O[nt][1] * inv0);
        *(__half2*)&g_af[row1 + c] = __floats2half2_rn(O[nt][2] * inv1, O[nt][3] * inv1);
    }
}

// ---------------- launch ----------------------------------------------------
extern "C" void kernel_launch(void* const* d_in, const int* in_sizes, int n_in,
                              void* d_out, int out_size) {
    const float* x   = (const float*)d_in[0];
    const float* w_q = (const float*)d_in[1];
    const float* b_q = (const float*)d_in[2];
    const float* w_k = (const float*)d_in[3];
    const float* b_k = (const float*)d_in[4];
    const float* w_v = (const float*)d_in[5];
    const float* b_v = (const float*)d_in[6];
    const float* w_o = (const float*)d_in[7];
    const float* b_o = (const float*)d_in[8];
    const float* a_q = (const float*)d_in[9];
    const float* u_q = (const float*)d_in[10];
    const float* a_k = (const float*)d_in[11];
    const float* u_k = (const float*)d_in[12];
    const float* a_v = (const float*)d_in[13];
    const float* u_v = (const float*)d_in[14];

    float* t_ptr;
    __half *xf, *wf, *af, *qh, *kh, *vh;
    cudaGetSymbolAddress((void**)&t_ptr, g_t);
    cudaGetSymbolAddress((void**)&xf, g_xf);
    cudaGetSymbolAddress((void**)&wf, g_wf);
    cudaGetSymbolAddress((void**)&af, g_af);
    cudaGetSymbolAddress((void**)&qh, g_qh);
    cudaGetSymbolAddress((void**)&kh, g_kh);
    cudaGetSymbolAddress((void**)&vh, g_vh);

    // 0+1) merged prep
    prep_kernel<<<4096 + MTOT / 32, 256>>>(x, w_q, w_k, w_v, w_o, a_q, a_k, a_v);

    // 2) merged QKV projections (256x128 CTAs, 512 threads)
    cudaFuncSetAttribute(gemm_qkv_kernel, cudaFuncAttributeMaxDynamicSharedMemorySize, GSMEM);
    cudaFuncSetAttribute(gemm_o_kernel, cudaFuncAttributeMaxDynamicSharedMemorySize, GSMEM);
    dim3 qkv_grid(DMODEL / 128, MTOT / 256, 3);
    gemm_qkv_kernel<<<qkv_grid, 512, GSMEM>>>(xf, wf, b_q, b_k, b_v, t_ptr,
                                              u_q, u_k, u_v, qh, kh, vh);

    // 3) attention (Br=64, occ 4, 2 tiles/iter)
    dim3 agrid(SEQ / 64, BATCH * NHEADS);
    attn_kernel<<<agrid, 128>>>();

    // 4) output projection
    dim3 ogrid(DMODEL / 128, MTOT / 256);
    gemm_o_kernel<<<ogrid, 512, GSMEM>>>(af, wf, b_o, (float*)d_out);
}